// round 11
// baseline (speedup 1.0000x reference)
#include <cuda_runtime.h>
#include <cuda_bf16.h>

#define S        8192
#define TPB      512
#define NWARP    (TPB / 32)          // 16 warps
#define NWORDS   (S / 32)            // 256 words per row
#define WPW      (NWORDS / NWARP)    // 16 words per warp segment
#define MAXROWS  2048

__device__ float    g_partial[MAXROWS];
__device__ float    g_count[MAXROWS];
__device__ unsigned g_done;          // zero-init; self-resets every pass

__global__ __launch_bounds__(TPB, 4)
void prox_loss_kernel(const float4* __restrict__ logits,
                      const int*    __restrict__ labels,
                      const float*  __restrict__ cw,
                      float*        __restrict__ out,
                      int nrows) {
    __shared__ float lut[2048];      // f1 by 11-bit true-window
    __shared__ float cw_s[4];
    __shared__ float ws0[NWARP], ws1[NWARP], ws2[NWARP], ws3[NWARP];
    __shared__ bool  s_is_last;

    const int tid  = threadIdx.x;
    const int lane = tid & 31;
    const int warp = tid >> 5;
    const int row  = blockIdx.x;

    const float NEG_LOG2_08 = -0.321928095f;   // log2(0.8)

    #pragma unroll
    for (int v = tid; v < 2048; v += TPB) {
        float f = 1.0f;
        if (!((v >> 5) & 1)) {                 // no true switch AT the position
            const unsigned fold = (__brev((unsigned)v & 31u) >> 27)
                                | (((unsigned)v >> 6) & 31u);  // bit(k-1)=dist k
            if (fold) f = exp2f((float)__ffs(fold) * NEG_LOG2_08);
        }
        lut[v] = f;
    }
    if (tid < 4) cw_s[tid] = __ldg(&cw[tid]);
    __syncthreads();

    const float4* lg = logits + (size_t)row * S;
    const int*    lb = labels + (size_t)row * S;

    const int W0 = warp * WPW;       // first word of this warp's segment

    // Pipeline state: prev/cur/next ballot words for 4 masks + cur/next ce.
    unsigned t2p, t3p, p2p, p3p;
    unsigned t2c, t3c, p2c, p3c;
    unsigned t2n, t3n, p2n, p3n;
    float    cec, cen;

    float base = 0.0f, C2 = 0.0f, C3 = 0.0f;
    int   cntI = 0;
    bool  has2 = false, has3 = false;

    // Load one 32-position word: CE for own lane + 4 ballot mask words.
    auto loadw = [&](int word, bool own,
                     unsigned& b2, unsigned& b3, unsigned& q2, unsigned& q3,
                     float& ce) {
        if ((unsigned)word < (unsigned)NWORDS) {
            const int p = (word << 5) + lane;
            const float4 l = __ldcs(&lg[p]);
            const int    y = __ldcs(&lb[p]);

            // first-occurrence argmax membership for classes 2/3 only
            const bool gwz = l.w > l.z;
            const bool p3b = (l.w > l.x) & (l.w > l.y) & gwz;
            const bool p2b = (l.z > l.x) & (l.z > l.y) & !gwz;

            // softmax without max-subtraction (logits ~ N(0,1): safe in fp32)
            const float esum = __expf(l.x) + __expf(l.y)
                             + __expf(l.z) + __expf(l.w);
            const float lse  = __logf(esum);

            const int ys = (y < 0) ? 0 : y;
            const float lya = (ys & 1) ? l.y : l.x;
            const float lyb = (ys & 1) ? l.w : l.z;
            const float ly  = (ys & 2) ? lyb : lya;
            ce = (y < 0) ? 0.0f : cw_s[ys] * (lse - ly);
            if (own) cntI += (y >= 0);

            b2 = __ballot_sync(0xFFFFFFFFu, y == 2);
            b3 = __ballot_sync(0xFFFFFFFFu, y == 3);
            q2 = __ballot_sync(0xFFFFFFFFu, p2b);
            q3 = __ballot_sync(0xFFFFFFFFu, p3b);
        } else {
            b2 = b3 = q2 = q3 = 0u;
            ce = 0.0f;
        }
    };

    // Prologue: halo word before the segment (ballots only), then first word.
    loadw(W0 - 1, false, t2p, t3p, p2p, p3p, cec);   // cec overwritten below
    loadw(W0,     true,  t2c, t3c, p2c, p3c, cec);

    const bool lo5 = (lane < 5);
    const int  shw = lo5 ? (lane + 27) : (lane - 5);

    #pragma unroll 2
    for (int i = 0; i < WPW; i++) {
        // Produce word i+1 (epilogue i=WPW-1 loads the halo word after the
        // segment; its ce/count are discarded via own=false).
        loadw(W0 + i + 1, (i + 1) < WPW, t2n, t3n, p2n, p3n, cen);

        // Finalize word i (positions p = (W0+i)*32 + lane).
        const unsigned y3 = (t3c >> lane) & 1u;
        const unsigned a3 = (p3c >> lane) & 1u;
        const unsigned tm = ((t2c | t3c) >> lane) & 1u;
        const unsigned pm = ((p2c | p3c) >> lane) & 1u;

        // 11-bit windows [p-5, p+5] from register words, funnel shift.
        const unsigned Ta = lo5 ? (a3 ? t3p : t2p) : (a3 ? t3c : t2c);
        const unsigned Tb = lo5 ? (a3 ? t3c : t2c) : (a3 ? t3n : t2n);
        const unsigned Pa = lo5 ? (y3 ? p3p : p2p) : (y3 ? p3c : p2c);
        const unsigned Pb = lo5 ? (y3 ? p3c : p2c) : (y3 ? p3n : p2n);
        const unsigned tw = __funnelshift_r(Ta, Tb, shw) & 0x7FFu;
        const unsigned pw = __funnelshift_r(Pa, Pb, shw) & 0x7FFu;

        const float f1  = pm ? lut[tw] : 1.0f;
        const float t   = cec * f1;
        // tfac assuming any_pred=true; exact correction added later:
        // any=false => pw==0 => f2a=1.5, +corr(0.5*t) gives exactly 2.0*t.
        const float f2a = tm ? (pw ? 1.0f : 1.5f) : 1.0f;
        base += t * f2a;
        const float corr = tm ? t * (2.0f - f2a) : 0.0f;
        C2 += y3 ? 0.0f : corr;
        C3 += y3 ? corr : 0.0f;

        has2 |= (p2c != 0u);
        has3 |= (p3c != 0u);

        // shift pipeline
        t2p = t2c; t3p = t3c; p2p = p2c; p3p = p3c;
        t2c = t2n; t3c = t3n; p2c = p2n; p3c = p3n;
        cec = cen;
    }

    const int any2 = __syncthreads_or((int)has2);
    const int any3 = __syncthreads_or((int)has3);

    float cnt = (float)cntI;
    #pragma unroll
    for (int o = 16; o > 0; o >>= 1) {
        base += __shfl_down_sync(0xFFFFFFFFu, base, o);
        C2   += __shfl_down_sync(0xFFFFFFFFu, C2,   o);
        C3   += __shfl_down_sync(0xFFFFFFFFu, C3,   o);
        cnt  += __shfl_down_sync(0xFFFFFFFFu, cnt,  o);
    }
    if (lane == 0) { ws0[warp] = base; ws1[warp] = C2; ws2[warp] = C3; ws3[warp] = cnt; }
    __syncthreads();
    if (warp == 0) {
        base = (lane < NWARP) ? ws0[lane] : 0.0f;
        C2   = (lane < NWARP) ? ws1[lane] : 0.0f;
        C3   = (lane < NWARP) ? ws2[lane] : 0.0f;
        cnt  = (lane < NWARP) ? ws3[lane] : 0.0f;
        #pragma unroll
        for (int o = 8; o > 0; o >>= 1) {
            base += __shfl_down_sync(0xFFFFFFFFu, base, o);
            C2   += __shfl_down_sync(0xFFFFFFFFu, C2,   o);
            C3   += __shfl_down_sync(0xFFFFFFFFu, C3,   o);
            cnt  += __shfl_down_sync(0xFFFFFFFFu, cnt,  o);
        }
        if (lane == 0) {
            const float rowsum = base + (any2 ? 0.0f : C2) + (any3 ? 0.0f : C3);
            g_partial[row] = rowsum;
            g_count[row]   = cnt;
            __threadfence();
            const unsigned prev = atomicAdd(&g_done, 1u);
            s_is_last = (prev == (unsigned)(nrows - 1));
        }
    }
    __syncthreads();

    // ---- Last block: global reduce + divide, reset counter ----
    if (s_is_last) {
        float s = 0.0f, c = 0.0f;
        for (int i = tid; i < nrows; i += TPB) {
            s += *((volatile float*)&g_partial[i]);
            c += *((volatile float*)&g_count[i]);
        }
        #pragma unroll
        for (int o = 16; o > 0; o >>= 1) {
            s += __shfl_down_sync(0xFFFFFFFFu, s, o);
            c += __shfl_down_sync(0xFFFFFFFFu, c, o);
        }
        if (lane == 0) { ws0[warp] = s; ws1[warp] = c; }
        __syncthreads();
        if (warp == 0) {
            s = (lane < NWARP) ? ws0[lane] : 0.0f;
            c = (lane < NWARP) ? ws1[lane] : 0.0f;
            #pragma unroll
            for (int o = 8; o > 0; o >>= 1) {
                s += __shfl_down_sync(0xFFFFFFFFu, s, o);
                c += __shfl_down_sync(0xFFFFFFFFu, c, o);
            }
            if (lane == 0) {
                out[0] = s / fmaxf(c, 1.0f);
                g_done = 0u;
            }
        }
    }
}

extern "C" void kernel_launch(void* const* d_in, const int* in_sizes, int n_in,
                              void* d_out, int out_size) {
    const float4* logits = (const float4*)d_in[0];
    const int*    labels = (const int*)d_in[1];
    const float*  cw     = (const float*)d_in[2];
    float*        out    = (float*)d_out;

    const int nrows = in_sizes[1] / S;   // B = 512

    prox_loss_kernel<<<nrows, TPB>>>(logits, labels, cw, out, nrows);
}

// round 12
// speedup vs baseline: 1.1380x; 1.1380x over previous
#include <cuda_runtime.h>
#include <cuda_bf16.h>

#define S        8192
#define TPB      256
#define HALF     (S / 2)             // 4096 positions per block
#define CHUNKS   (HALF / TPB)        // 16
#define NWARP    (TPB / 32)          // 8 warps
#define NWH      (HALF / 32)         // 128 mask words per half-row
#define MAXBLK   4096

__device__ float    g_base[MAXBLK];
__device__ float    g_C2[MAXBLK];
__device__ float    g_C3[MAXBLK];
__device__ float    g_cnt[MAXBLK];
__device__ int      g_any[MAXBLK];   // bit0 = any pred2, bit1 = any pred3
__device__ unsigned g_done;          // zero-init; self-resets every pass

__global__ __launch_bounds__(TPB, 8)
void prox_loss_kernel(const float4* __restrict__ logits,
                      const int*    __restrict__ labels,
                      const float*  __restrict__ cw,
                      float*        __restrict__ out,
                      int nrows) {
    // M[0]=true2, M[1]=true3, M[2]=pred2, M[3]=pred3; padded: [0] and [NWH+1]
    // hold REAL halo words from the neighboring half (or 0 at row ends).
    __shared__ unsigned M[4][NWH + 2];
    __shared__ float    ce_s[HALF];              // 16 KB
    __shared__ float    lut[2048];               // f1 by 11-bit true-window
    __shared__ float    cw_s[4];
    __shared__ float    ws0[NWARP], ws1[NWARP], ws2[NWARP], ws3[NWARP];
    __shared__ bool     s_is_last;

    const int bid  = blockIdx.x;
    const int row  = bid >> 1;
    const int half = bid & 1;
    const int tid  = threadIdx.x;
    const int lane = tid & 31;
    const int warp = tid >> 5;

    const float NEG_LOG2_08 = -0.321928095f;     // log2(0.8)

    // ---- LUT + cw init ----
    #pragma unroll
    for (int v = tid; v < 2048; v += TPB) {
        float f = 1.0f;
        if (!((v >> 5) & 1)) {                   // no true switch AT the position
            const unsigned fold = (__brev((unsigned)v & 31u) >> 27)
                                | (((unsigned)v >> 6) & 31u);  // bit(k-1)=dist k
            if (fold) f = exp2f((float)__ffs(fold) * NEG_LOG2_08);
        }
        lut[v] = f;
    }
    if (tid < 4) cw_s[tid] = __ldg(&cw[tid]);
    __syncthreads();

    const float4* lg = logits + (size_t)row * S;
    const int*    lb = labels + (size_t)row * S;
    const int     gbase = half * HALF;           // row-global offset of this half

    float cnt = 0.0f;
    bool  hasp2 = false, hasp3 = false;

    // ---- Phase 1: own 4096 positions -> ce_s + ballot masks ----
    #pragma unroll 4
    for (int c = 0; c < CHUNKS; c++) {
        const int pl = c * TPB + tid;            // local position 0..4095
        const int gp = gbase + pl;
        const float4 l = __ldcs(&lg[gp]);
        const int    y = __ldcs(&lb[gp]);

        const bool gwz = l.w > l.z;
        const bool p3b = (l.w > l.x) & (l.w > l.y) & gwz;
        const bool p2b = (l.z > l.x) & (l.z > l.y) & !gwz;

        const float esum = __expf(l.x) + __expf(l.y) + __expf(l.z) + __expf(l.w);
        const float lse  = __logf(esum);

        const int ys = (y < 0) ? 0 : y;
        const float lya = (ys & 1) ? l.y : l.x;
        const float lyb = (ys & 1) ? l.w : l.z;
        const float ly  = (ys & 2) ? lyb : lya;
        ce_s[pl] = (y < 0) ? 0.0f : cw_s[ys] * (lse - ly);

        const bool t3b = (y == 3);
        const unsigned bt2 = __ballot_sync(0xFFFFFFFFu, y == 2);
        const unsigned bt3 = __ballot_sync(0xFFFFFFFFu, t3b);
        const unsigned bp2 = __ballot_sync(0xFFFFFFFFu, p2b);
        const unsigned bp3 = __ballot_sync(0xFFFFFFFFu, p3b);
        const unsigned bv  = __ballot_sync(0xFFFFFFFFu, y >= 0);
        hasp2 |= (bp2 != 0u);
        hasp3 |= (bp3 != 0u);
        if (lane == 0) {
            const int wi = (pl >> 5) + 1;
            M[0][wi] = bt2; M[1][wi] = bt3; M[2][wi] = bp2; M[3][wi] = bp3;
            cnt += (float)__popc(bv);
        }
    }

    // ---- Halo words: warp 0 -> word before segment, warp 1 -> word after ----
    if (warp < 2) {
        const int w  = (warp == 0) ? -1 : NWH;   // local word index
        const int gp = gbase + (w << 5) + lane;  // row-global position
        bool t2b = false, t3b = false, p2b = false, p3b = false;
        if ((unsigned)gp < (unsigned)S) {
            const float4 l = lg[gp];
            const int    y = lb[gp];
            const bool gwz = l.w > l.z;
            p3b = (l.w > l.x) & (l.w > l.y) & gwz;
            p2b = (l.z > l.x) & (l.z > l.y) & !gwz;
            t2b = (y == 2);
            t3b = (y == 3);
        }
        const unsigned bt2 = __ballot_sync(0xFFFFFFFFu, t2b);
        const unsigned bt3 = __ballot_sync(0xFFFFFFFFu, t3b);
        const unsigned bp2 = __ballot_sync(0xFFFFFFFFu, p2b);
        const unsigned bp3 = __ballot_sync(0xFFFFFFFFu, p3b);
        if (lane == 0) {
            const int wi = w + 1;                // 0 or NWH+1
            M[0][wi] = bt2; M[1][wi] = bt3; M[2][wi] = bp2; M[3][wi] = bp3;
        }
    }

    __syncthreads();

    float base = 0.0f, C2 = 0.0f, C3 = 0.0f;

    // ---- Phase 2: windows + LUT; tfac deferred via base/C2/C3 split ----
    #pragma unroll 4
    for (int c = 0; c < CHUNKS; c++) {
        const int pl = c * TPB + tid;
        const int wi = (pl >> 5) + 1;

        const unsigned t2c = M[0][wi], t3c = M[1][wi];
        const unsigned p2c = M[2][wi], p3c = M[3][wi];

        const unsigned y3 = (t3c >> lane) & 1u;
        const unsigned a3 = (p3c >> lane) & 1u;
        const unsigned tm = ((t2c | t3c) >> lane) & 1u;
        const unsigned pm = ((p2c | p3c) >> lane) & 1u;

        const int bpp = pl + 27;                 // padded bitspace start
        const int wi0 = bpp >> 5;
        const int sh  = bpp & 31;

        const unsigned tw = __funnelshift_r(M[a3][wi0], M[a3][wi0 + 1], sh) & 0x7FFu;
        const unsigned pw = __funnelshift_r(M[2 + y3][wi0], M[2 + y3][wi0 + 1], sh) & 0x7FFu;

        const float f1 = pm ? lut[tw] : 1.0f;
        const float t  = ce_s[pl] * f1;
        // tfac assuming any_pred=true; correction restores 2.0 when any=false
        // (any=false => pw==0 => f2a=1.5; +0.5*t gives exactly 2.0*t).
        const float f2a = tm ? (pw ? 1.0f : 1.5f) : 1.0f;
        base += t * f2a;
        const float corr = tm ? t * (2.0f - f2a) : 0.0f;
        C2 += y3 ? 0.0f : corr;
        C3 += y3 ? corr : 0.0f;
    }

    const int hp2 = __syncthreads_or(hasp2 ? 1 : 0);
    const int hp3 = __syncthreads_or(hasp3 ? 1 : 0);

    // ---- Block reduction of (base, C2, C3, cnt) ----
    #pragma unroll
    for (int o = 16; o > 0; o >>= 1) {
        base += __shfl_down_sync(0xFFFFFFFFu, base, o);
        C2   += __shfl_down_sync(0xFFFFFFFFu, C2,   o);
        C3   += __shfl_down_sync(0xFFFFFFFFu, C3,   o);
        cnt  += __shfl_down_sync(0xFFFFFFFFu, cnt,  o);
    }
    if (lane == 0) { ws0[warp] = base; ws1[warp] = C2; ws2[warp] = C3; ws3[warp] = cnt; }
    __syncthreads();
    if (warp == 0) {
        base = (lane < NWARP) ? ws0[lane] : 0.0f;
        C2   = (lane < NWARP) ? ws1[lane] : 0.0f;
        C3   = (lane < NWARP) ? ws2[lane] : 0.0f;
        cnt  = (lane < NWARP) ? ws3[lane] : 0.0f;
        #pragma unroll
        for (int o = 4; o > 0; o >>= 1) {
            base += __shfl_down_sync(0xFFFFFFFFu, base, o);
            C2   += __shfl_down_sync(0xFFFFFFFFu, C2,   o);
            C3   += __shfl_down_sync(0xFFFFFFFFu, C3,   o);
            cnt  += __shfl_down_sync(0xFFFFFFFFu, cnt,  o);
        }
        if (lane == 0) {
            g_base[bid] = base;
            g_C2[bid]   = C2;
            g_C3[bid]   = C3;
            g_cnt[bid]  = cnt;
            g_any[bid]  = (hp2 ? 1 : 0) | (hp3 ? 2 : 0);
            __threadfence();
            const unsigned prev = atomicAdd(&g_done, 1u);
            s_is_last = (prev == (unsigned)(2 * nrows - 1));
        }
    }
    __syncthreads();

    // ---- Last block: per-row combine + global reduce + divide ----
    if (s_is_last) {
        float s = 0.0f, c = 0.0f;
        for (int r = tid; r < nrows; r += TPB) {
            const int b0 = 2 * r, b1 = 2 * r + 1;
            const int any = *((volatile int*)&g_any[b0]) | *((volatile int*)&g_any[b1]);
            float rs = *((volatile float*)&g_base[b0]) + *((volatile float*)&g_base[b1]);
            if (!(any & 1)) rs += *((volatile float*)&g_C2[b0]) + *((volatile float*)&g_C2[b1]);
            if (!(any & 2)) rs += *((volatile float*)&g_C3[b0]) + *((volatile float*)&g_C3[b1]);
            s += rs;
            c += *((volatile float*)&g_cnt[b0]) + *((volatile float*)&g_cnt[b1]);
        }
        #pragma unroll
        for (int o = 16; o > 0; o >>= 1) {
            s += __shfl_down_sync(0xFFFFFFFFu, s, o);
            c += __shfl_down_sync(0xFFFFFFFFu, c, o);
        }
        if (lane == 0) { ws0[warp] = s; ws1[warp] = c; }
        __syncthreads();
        if (warp == 0) {
            s = (lane < NWARP) ? ws0[lane] : 0.0f;
            c = (lane < NWARP) ? ws1[lane] : 0.0f;
            #pragma unroll
            for (int o = 4; o > 0; o >>= 1) {
                s += __shfl_down_sync(0xFFFFFFFFu, s, o);
                c += __shfl_down_sync(0xFFFFFFFFu, c, o);
            }
            if (lane == 0) {
                out[0] = s / fmaxf(c, 1.0f);
                g_done = 0u;
            }
        }
    }
}

extern "C" void kernel_launch(void* const* d_in, const int* in_sizes, int n_in,
                              void* d_out, int out_size) {
    const float4* logits = (const float4*)d_in[0];
    const int*    labels = (const int*)d_in[1];
    const float*  cw     = (const float*)d_in[2];
    float*        out    = (float*)d_out;

    const int nrows = in_sizes[1] / S;   // B = 512

    prox_loss_kernel<<<2 * nrows, TPB>>>(logits, labels, cw, out, nrows);
}